// round 3
// baseline (speedup 1.0000x reference)
#include <cuda_runtime.h>
#include <cstdint>

#define NU 50000
#define NI 25000
#define DIMV 128
#define GROWS 16

#define UF ((size_t)NU * DIMV)
#define IFl ((size_t)NI * DIMV)

// ------------------- unified device scratch (no allocs) -------------------
// layout (floats):
//  accc[3UF] | sacc[UF] | iacc[IF]     <- zero-group 1
//  curA[3UF] | i1[IF]   | s1[UF]       <- zero-group 2
//  curB[3UF] | i2[IF]   | s2[UF]       <- zero-group 3
//  gate[4UF] | mixed[UF]
#define O_ACCC ((size_t)0)
#define O_SACC (3 * UF)
#define O_IACC (4 * UF)
#define O_CURA (4 * UF + IFl)
#define O_I1   (7 * UF + IFl)
#define O_S1   (7 * UF + 2 * IFl)
#define O_CURB (8 * UF + 2 * IFl)
#define O_I2   (11 * UF + 2 * IFl)
#define O_S2   (11 * UF + 3 * IFl)
#define O_GATE (12 * UF + 3 * IFl)
#define O_MIX  (16 * UF + 3 * IFl)
#define TOTALF (17 * UF + 3 * IFl)

__device__ __align__(16) float g_buf[TOTALF];
__device__ float g_attvec[DIMV];

// ------------------- attention vector: v = M @ a -------------------
__global__ void attvec_kernel(const float* __restrict__ att, const float* __restrict__ mat) {
    int j = threadIdx.x;
    float s = 0.f;
#pragma unroll 8
    for (int d = 0; d < DIMV; d++) s += mat[j * DIMV + d] * att[d];
    g_attvec[j] = s;
}

// ------------------- gating: G_c = U * sigmoid(U @ W_c + b_c) -------------------
__global__ void __launch_bounds__(128) gate_kernel(const float* __restrict__ U,
                                                   const float* __restrict__ W4,
                                                   const float* __restrict__ B4,
                                                   float* __restrict__ gate_out) {
    extern __shared__ float sm[];
    float* Wt = sm;              // [128][132]
    float* Us = sm + DIMV * 132; // [GROWS][128]
    int t = threadIdx.x;
    int c = blockIdx.y;
    const float* W = W4 + c * DIMV * DIMV;
    float b = B4[c * DIMV + t];
    float* out = gate_out + (size_t)c * UF;

    for (int k = 0; k < DIMV; k++) Wt[t * 132 + k] = W[k * DIMV + t];

    for (int r0 = blockIdx.x * GROWS; r0 < NU; r0 += gridDim.x * GROWS) {
        __syncthreads();
#pragma unroll
        for (int r = 0; r < GROWS; r++) Us[r * DIMV + t] = U[(size_t)(r0 + r) * DIMV + t];
        __syncthreads();
        float acc[GROWS];
#pragma unroll
        for (int r = 0; r < GROWS; r++) acc[r] = b;
#pragma unroll 4
        for (int k = 0; k < DIMV; k += 4) {
            float4 w = *(const float4*)&Wt[t * 132 + k];
#pragma unroll
            for (int r = 0; r < GROWS; r++) {
                float4 u = *(const float4*)&Us[r * DIMV + k];
                acc[r] += u.x * w.x;
                acc[r] += u.y * w.y;
                acc[r] += u.z * w.z;
                acc[r] += u.w * w.w;
            }
        }
#pragma unroll
        for (int r = 0; r < GROWS; r++) {
            float uv = Us[r * DIMV + t];
            out[(size_t)(r0 + r) * DIMV + t] = uv / (1.f + expf(-acc[r]));
        }
    }
}

// ------------------- batched COO SpMM -------------------
__device__ __forceinline__ void red_add_v4(float* p, float a, float b, float c, float d) {
    asm volatile("red.global.add.v4.f32 [%0], {%1, %2, %3, %4};"
                 :: "l"(p), "f"(a), "f"(b), "f"(c), "f"(d) : "memory");
}

struct SpmmJob { const int* r; const int* c; const float* v; const float* X; float* Y; };
struct Spmm3Args { SpmmJob j[3]; };

// warp handles 32 consecutive edges; indices loaded coalesced, spread via shfl;
// inner loop unrolled x4 for gather MLP before the REDs.
__device__ __forceinline__ void spmm_body(const int* __restrict__ rows, const int* __restrict__ cols,
                                          const float* __restrict__ vals, const float* __restrict__ X,
                                          float* __restrict__ Y, int ne) {
    int warp = (int)((blockIdx.x * (unsigned)blockDim.x + threadIdx.x) >> 5);
    int lane = threadIdx.x & 31;
    int e0 = warp << 5;
    if (e0 >= ne) return;
    const unsigned FM = 0xffffffffu;
    int idx = e0 + lane; if (idx > ne - 1) idx = ne - 1;
    int r = __ldg(rows + idx);
    int c = __ldg(cols + idx);
    float v = __ldg(vals + idx);
    int nthis = ne - e0; if (nthis > 32) nthis = 32;
    if (nthis == 32) {
#pragma unroll
        for (int j = 0; j < 32; j += 4) {
            int c0 = __shfl_sync(FM, c, j + 0);
            int c1 = __shfl_sync(FM, c, j + 1);
            int c2 = __shfl_sync(FM, c, j + 2);
            int c3 = __shfl_sync(FM, c, j + 3);
            float4 x0 = __ldg((const float4*)(X + (size_t)c0 * DIMV) + lane);
            float4 x1 = __ldg((const float4*)(X + (size_t)c1 * DIMV) + lane);
            float4 x2 = __ldg((const float4*)(X + (size_t)c2 * DIMV) + lane);
            float4 x3 = __ldg((const float4*)(X + (size_t)c3 * DIMV) + lane);
            int r0 = __shfl_sync(FM, r, j + 0);
            int r1 = __shfl_sync(FM, r, j + 1);
            int r2 = __shfl_sync(FM, r, j + 2);
            int r3 = __shfl_sync(FM, r, j + 3);
            float v0 = __shfl_sync(FM, v, j + 0);
            float v1 = __shfl_sync(FM, v, j + 1);
            float v2 = __shfl_sync(FM, v, j + 2);
            float v3 = __shfl_sync(FM, v, j + 3);
            red_add_v4(Y + (size_t)r0 * DIMV + lane * 4, v0 * x0.x, v0 * x0.y, v0 * x0.z, v0 * x0.w);
            red_add_v4(Y + (size_t)r1 * DIMV + lane * 4, v1 * x1.x, v1 * x1.y, v1 * x1.z, v1 * x1.w);
            red_add_v4(Y + (size_t)r2 * DIMV + lane * 4, v2 * x2.x, v2 * x2.y, v2 * x2.z, v2 * x2.w);
            red_add_v4(Y + (size_t)r3 * DIMV + lane * 4, v3 * x3.x, v3 * x3.y, v3 * x3.z, v3 * x3.w);
        }
    } else {
        for (int j = 0; j < nthis; j++) {
            int cj = __shfl_sync(FM, c, j);
            int rj = __shfl_sync(FM, r, j);
            float vj = __shfl_sync(FM, v, j);
            float4 x = __ldg((const float4*)(X + (size_t)cj * DIMV) + lane);
            red_add_v4(Y + (size_t)rj * DIMV + lane * 4, vj * x.x, vj * x.y, vj * x.z, vj * x.w);
        }
    }
}

__global__ void __launch_bounds__(256) spmm_multi_kernel(Spmm3Args a, int ne) {
    SpmmJob jb = a.j[blockIdx.y];
    spmm_body(jb.r, jb.c, jb.v, jb.X, jb.Y, ne);
}

// ------------------- acc += l2norm(src), fused 5 jobs -------------------
struct L2Job { const float* src; float* acc; int n; };
struct L2Args { L2Job j[5]; };

__global__ void __launch_bounds__(256) l2acc5_kernel(L2Args a) {
    L2Job jb = a.j[blockIdx.y];
    int w = (int)((blockIdx.x * (unsigned)blockDim.x + threadIdx.x) >> 5);
    int lane = threadIdx.x & 31;
    if (w >= jb.n) return;
    size_t base = (size_t)w * DIMV + lane * 4;
    float4 x = *(const float4*)(jb.src + base);
    float ss = x.x * x.x + x.y * x.y + x.z * x.z + x.w * x.w;
#pragma unroll
    for (int o = 16; o; o >>= 1) ss += __shfl_xor_sync(0xffffffffu, ss, o);
    float sc = rsqrtf(fmaxf(ss, 1e-12f));
    float4 acc = *(const float4*)(jb.acc + base);
    acc.x += x.x * sc; acc.y += x.y * sc; acc.z += x.z * sc; acc.w += x.w * sc;
    *(float4*)(jb.acc + base) = acc;
}

// ------------------- channel attention mix -------------------
__global__ void __launch_bounds__(256) mix_kernel(
        const float* __restrict__ C0, const float* __restrict__ C1, const float* __restrict__ C2,
        const float* __restrict__ A0, const float* __restrict__ A1, const float* __restrict__ A2,
        const float* __restrict__ S, const float* __restrict__ S2,
        float* __restrict__ out, int nrows) {
    int w = (int)((blockIdx.x * (unsigned)blockDim.x + threadIdx.x) >> 5);
    int lane = threadIdx.x & 31;
    if (w >= nrows) return;
    size_t base = (size_t)w * DIMV + lane * 4;
    float4 v = *(const float4*)(g_attvec + lane * 4);
    float4 c0 = *(const float4*)(C0 + base);
    float4 c1 = *(const float4*)(C1 + base);
    float4 c2 = *(const float4*)(C2 + base);
    if (A0) {
        float4 a0 = *(const float4*)(A0 + base);
        float4 a1 = *(const float4*)(A1 + base);
        float4 a2 = *(const float4*)(A2 + base);
        c0.x += a0.x; c0.y += a0.y; c0.z += a0.z; c0.w += a0.w;
        c1.x += a1.x; c1.y += a1.y; c1.z += a1.z; c1.w += a1.w;
        c2.x += a2.x; c2.y += a2.y; c2.z += a2.z; c2.w += a2.w;
    }
    float w0 = c0.x * v.x + c0.y * v.y + c0.z * v.z + c0.w * v.w;
    float w1 = c1.x * v.x + c1.y * v.y + c1.z * v.z + c1.w * v.w;
    float w2 = c2.x * v.x + c2.y * v.y + c2.z * v.z + c2.w * v.w;
#pragma unroll
    for (int o = 16; o; o >>= 1) {
        w0 += __shfl_xor_sync(0xffffffffu, w0, o);
        w1 += __shfl_xor_sync(0xffffffffu, w1, o);
        w2 += __shfl_xor_sync(0xffffffffu, w2, o);
    }
    float m = fmaxf(w0, fmaxf(w1, w2));
    float e0 = expf(w0 - m), e1 = expf(w1 - m), e2 = expf(w2 - m);
    float inv = 1.f / (e0 + e1 + e2);
    e0 *= inv; e1 *= inv; e2 *= inv;
    float4 s = *(const float4*)(S + base);
    if (S2) {
        float4 s2 = *(const float4*)(S2 + base);
        s.x += s2.x; s.y += s2.y; s.z += s2.z; s.w += s2.w;
    }
    float4 o;
    o.x = e0 * c0.x + e1 * c1.x + e2 * c2.x + 0.5f * s.x;
    o.y = e0 * c0.y + e1 * c1.y + e2 * c2.y + 0.5f * s.y;
    o.z = e0 * c0.z + e1 * c1.z + e2 * c2.z + 0.5f * s.z;
    o.w = e0 * c0.w + e1 * c1.w + e2 * c2.w + 0.5f * s.w;
    *(float4*)(out + base) = o;
}

// ------------------- item output: out = i_emb + iacc -------------------
__global__ void __launch_bounds__(256) item_out_kernel(const float* __restrict__ ie,
                                                       const float* __restrict__ ia,
                                                       float* __restrict__ out) {
    int i = blockIdx.x * blockDim.x + threadIdx.x;
    if (i < (int)(IFl / 4)) {
        float4 a = __ldg((const float4*)ie + i);
        float4 b = *((const float4*)ia + i);
        a.x += b.x; a.y += b.y; a.z += b.z; a.w += b.w;
        *((float4*)out + i) = a;
    }
}

// ------------------- host orchestration -------------------
extern "C" void kernel_launch(void* const* d_in, const int* in_sizes, int n_in,
                              void* d_out, int out_size) {
    const float* u_emb = (const float*)d_in[0];
    const float* i_emb = (const float*)d_in[1];
    const float* gW = (const float*)d_in[2];
    const float* gB = (const float*)d_in[3];
    const float* att = (const float*)d_in[4];
    const float* attm = (const float*)d_in[5];
    const int* Hr[3] = {(const int*)d_in[6], (const int*)d_in[9], (const int*)d_in[12]};
    const int* Hc[3] = {(const int*)d_in[7], (const int*)d_in[10], (const int*)d_in[13]};
    const float* Hv[3] = {(const float*)d_in[8], (const float*)d_in[11], (const float*)d_in[14]};
    const int* Rr = (const int*)d_in[15];
    const int* Rc = (const int*)d_in[16];
    const float* Rv = (const float*)d_in[17];
    int EH = in_sizes[6], ER = in_sizes[15];
    float* out = (float*)d_out;

    // one-time host-side setup (cached; keeps capture path launch-only)
    static float* B = nullptr;
    static size_t smem = (size_t)(DIMV * 132 + GROWS * DIMV) * sizeof(float);
    if (!B) {
        cudaGetSymbolAddress((void**)&B, g_buf);
        cudaFuncSetAttribute(gate_kernel, cudaFuncAttributeMaxDynamicSharedMemorySize, (int)smem);
    }
    float* accc = B + O_ACCC;
    float* sacc = B + O_SACC;
    float* iacc = B + O_IACC;
    float* curA = B + O_CURA;
    float* i1 = B + O_I1;
    float* s1 = B + O_S1;
    float* curB = B + O_CURB;
    float* i2 = B + O_I2;
    float* s2 = B + O_S2;
    float* gate = B + O_GATE;
    float* mixed = B + O_MIX;

#define GP(c) (gate + (size_t)(c) * UF)
#define CA(c) (curA + (size_t)(c) * UF)
#define CB(c) (curB + (size_t)(c) * UF)
#define AC(c) (accc + (size_t)(c) * UF)

    const size_t GRP = (4 * UF + IFl) * sizeof(float);  // one zero-group

    cudaMemsetAsync(B + O_ACCC, 0, GRP);
    attvec_kernel<<<1, 128>>>(att, attm);
    gate_kernel<<<dim3(448, 4), 128, smem>>>(u_emb, gW, gB, gate);

    int mixb = (NU + 7) / 8;
    int l2b = (NU + 7) / 8;
    int spH = (EH + 255) / 256;   // 8 warps/block, 32 edges/warp
    int spR = (ER + 255) / 256;

    // ---------------- layer 1 ----------------
    mix_kernel<<<mixb, 256>>>(GP(0), GP(1), GP(2), nullptr, nullptr, nullptr,
                              GP(3), nullptr, mixed, NU);
    cudaMemsetAsync(B + O_CURA, 0, GRP);
    {
        Spmm3Args a;
        for (int k = 0; k < 3; k++) a.j[k] = {Hr[k], Hc[k], Hv[k], GP(k), CA(k)};
        spmm_multi_kernel<<<dim3(spH, 3), 256>>>(a, EH);
        Spmm3Args r;
        r.j[0] = {Rc, Rr, Rv, mixed, i1};   // new_item = R^T @ mixed
        r.j[1] = {Rr, Rc, Rv, i_emb, s1};   // cur_s = R @ i_emb
        r.j[2] = r.j[0];
        spmm_multi_kernel<<<dim3(spR, 2), 256>>>(r, ER);
    }
    {
        L2Args a;
        for (int k = 0; k < 3; k++) a.j[k] = {CA(k), AC(k), NU};
        a.j[3] = {i1, iacc, NI};
        a.j[4] = {s1, sacc, NU};
        l2acc5_kernel<<<dim3(l2b, 5), 256>>>(a);
    }

    // ---------------- layer 2 ----------------
    mix_kernel<<<mixb, 256>>>(CA(0), CA(1), CA(2), nullptr, nullptr, nullptr,
                              s1, nullptr, mixed, NU);
    cudaMemsetAsync(B + O_CURB, 0, GRP);
    {
        Spmm3Args a;
        for (int k = 0; k < 3; k++) a.j[k] = {Hr[k], Hc[k], Hv[k], CA(k), CB(k)};
        spmm_multi_kernel<<<dim3(spH, 3), 256>>>(a, EH);
        Spmm3Args r;
        r.j[0] = {Rc, Rr, Rv, mixed, i2};   // new_item2 = R^T @ mixed2
        r.j[1] = {Rr, Rc, Rv, i1, s2};      // cur_s2 = R @ item1
        r.j[2] = r.j[0];
        spmm_multi_kernel<<<dim3(spR, 2), 256>>>(r, ER);
    }
    {
        L2Args a;
        for (int k = 0; k < 3; k++) a.j[k] = {CB(k), AC(k), NU};
        a.j[3] = {i2, iacc, NI};
        a.j[4] = {s2, sacc, NU};
        l2acc5_kernel<<<dim3(l2b, 5), 256>>>(a);
    }

    // ---------------- final ----------------
    mix_kernel<<<mixb, 256>>>(GP(0), GP(1), GP(2), AC(0), AC(1), AC(2),
                              GP(3), sacc, out, NU);
    item_out_kernel<<<(int)((IFl / 4 + 255) / 256), 256>>>(i_emb, iacc, out + (size_t)NU * DIMV);
}

// round 4
// speedup vs baseline: 1.5349x; 1.5349x over previous
#include <cuda_runtime.h>
#include <cstdint>

#define NU 50000
#define NI 25000
#define DIMV 128
#define GROWS 16
#define EHMAX 600000
#define ERMAX 1000000

#define UF ((size_t)NU * DIMV)
#define IFl ((size_t)NI * DIMV)

// ------------------- unified float scratch -------------------
// accc[3UF] | sacc[UF] | iacc[IF]   <- zero-group
// curA[3UF] | i1[IF] | s1[UF] | gate[4UF] | mixed[UF]
#define O_ACCC ((size_t)0)
#define O_SACC (3 * UF)
#define O_IACC (4 * UF)
#define O_CURA (4 * UF + IFl)
#define O_I1   (7 * UF + IFl)
#define O_S1   (7 * UF + 2 * IFl)
#define O_GATE (8 * UF + 2 * IFl)
#define O_MIX  (12 * UF + 2 * IFl)
#define TOTALF (13 * UF + 2 * IFl)

__device__ __align__(16) float g_buf[TOTALF];
__device__ float g_attvec[DIMV];

// ------------------- CSR scratch -------------------
// jobs: 0..2 = H0..H2 (NU rows), 3 = R (NU rows), 4 = RT (NI rows)
#define CNT_TOT (4 * NU + NI)
#define OFFS_TOT (4 * (NU + 1) + (NI + 1))
#define PE_TOT (3 * EHMAX + 2 * ERMAX)
__device__ int g_cnt[CNT_TOT];
__device__ int g_cur[CNT_TOT];
__device__ int g_offs[OFFS_TOT];
__device__ int g_pcol[PE_TOT];
__device__ float g_pval[PE_TOT];

// ------------------- attention vector: v = M @ a -------------------
__global__ void attvec_kernel(const float* __restrict__ att, const float* __restrict__ mat) {
    int j = threadIdx.x;
    float s = 0.f;
#pragma unroll 8
    for (int d = 0; d < DIMV; d++) s += mat[j * DIMV + d] * att[d];
    g_attvec[j] = s;
}

// ------------------- gating -------------------
__global__ void __launch_bounds__(128) gate_kernel(const float* __restrict__ U,
                                                   const float* __restrict__ W4,
                                                   const float* __restrict__ B4,
                                                   float* __restrict__ gate_out) {
    extern __shared__ float sm[];
    float* Wt = sm;
    float* Us = sm + DIMV * 132;
    int t = threadIdx.x;
    int c = blockIdx.y;
    const float* W = W4 + c * DIMV * DIMV;
    float b = B4[c * DIMV + t];
    float* out = gate_out + (size_t)c * UF;

    for (int k = 0; k < DIMV; k++) Wt[t * 132 + k] = W[k * DIMV + t];

    for (int r0 = blockIdx.x * GROWS; r0 < NU; r0 += gridDim.x * GROWS) {
        __syncthreads();
#pragma unroll
        for (int r = 0; r < GROWS; r++) Us[r * DIMV + t] = U[(size_t)(r0 + r) * DIMV + t];
        __syncthreads();
        float acc[GROWS];
#pragma unroll
        for (int r = 0; r < GROWS; r++) acc[r] = b;
#pragma unroll 4
        for (int k = 0; k < DIMV; k += 4) {
            float4 w = *(const float4*)&Wt[t * 132 + k];
#pragma unroll
            for (int r = 0; r < GROWS; r++) {
                float4 u = *(const float4*)&Us[r * DIMV + k];
                acc[r] += u.x * w.x;
                acc[r] += u.y * w.y;
                acc[r] += u.z * w.z;
                acc[r] += u.w * w.w;
            }
        }
#pragma unroll
        for (int r = 0; r < GROWS; r++) {
            float uv = Us[r * DIMV + t];
            out[(size_t)(r0 + r) * DIMV + t] = uv / (1.f + expf(-acc[r]));
        }
    }
}

// ------------------- CSR build -------------------
struct BuildJob { const int* rows; const int* cols; const float* vals;
                  int* cnt; int* cur; int* offs; int* pcol; float* pval; int ne; int nrows; };
struct Build5 { BuildJob j[5]; };

__global__ void __launch_bounds__(256) count_kernel(Build5 a) {
    BuildJob jb = a.j[blockIdx.y];
    int e = blockIdx.x * 256 + threadIdx.x;
    if (e < jb.ne) atomicAdd(jb.cnt + __ldg(jb.rows + e), 1);
}

__global__ void __launch_bounds__(1024) scan_kernel(Build5 a) {
    BuildJob jb = a.j[blockIdx.x];
    const int* cnt = jb.cnt;
    int* offs = jb.offs;
    int* cur = jb.cur;
    int n = jb.nrows;
    __shared__ int sm[1024];
    int tid = threadIdx.x;
    int carry = 0;
    for (int base = 0; base < n; base += 1024) {
        int i = base + tid;
        int v = (i < n) ? cnt[i] : 0;
        sm[tid] = v;
        __syncthreads();
        for (int o = 1; o < 1024; o <<= 1) {
            int t = (tid >= o) ? sm[tid - o] : 0;
            __syncthreads();
            sm[tid] += t;
            __syncthreads();
        }
        int incl = sm[tid];
        int excl = incl - v;
        if (i < n) { offs[i] = carry + excl; cur[i] = carry + excl; }
        carry += sm[1023];
        __syncthreads();
    }
    if (tid == 0) offs[n] = carry;
}

__global__ void __launch_bounds__(256) scatter_kernel(Build5 a) {
    BuildJob jb = a.j[blockIdx.y];
    int e = blockIdx.x * 256 + threadIdx.x;
    if (e >= jb.ne) return;
    int r = __ldg(jb.rows + e);
    int p = atomicAdd(jb.cur + r, 1);
    jb.pcol[p] = __ldg(jb.cols + e);
    jb.pval[p] = __ldg(jb.vals + e);
}

// ------------------- CSR SpMM, warp per row, fused l2norm-accumulate -------------------
struct CsrJob { const int* offs; const int* pcol; const float* pval;
                const float* X; float* Y; float* acc; int nrows; };
struct Csr3 { CsrJob j[3]; };

__device__ __forceinline__ void csr_body(const CsrJob& jb) {
    int w = (int)((blockIdx.x * (unsigned)blockDim.x + threadIdx.x) >> 5);
    int lane = threadIdx.x & 31;
    if (w >= jb.nrows) return;
    const unsigned FM = 0xffffffffu;
    int start = __ldg(jb.offs + w);
    int end = __ldg(jb.offs + w + 1);
    float4 acc = make_float4(0.f, 0.f, 0.f, 0.f);
    const float* X = jb.X;
    for (int b = start; b < end; b += 32) {
        int i = b + lane;
        int c = 0; float v = 0.f;
        if (i < end) { c = __ldg(jb.pcol + i); v = __ldg(jb.pval + i); }
        int m = end - b; if (m > 32) m = 32;
        int j = 0;
        for (; j + 4 <= m; j += 4) {
            int c0 = __shfl_sync(FM, c, j + 0);
            int c1 = __shfl_sync(FM, c, j + 1);
            int c2 = __shfl_sync(FM, c, j + 2);
            int c3 = __shfl_sync(FM, c, j + 3);
            float4 x0 = __ldg((const float4*)(X + (size_t)c0 * DIMV) + lane);
            float4 x1 = __ldg((const float4*)(X + (size_t)c1 * DIMV) + lane);
            float4 x2 = __ldg((const float4*)(X + (size_t)c2 * DIMV) + lane);
            float4 x3 = __ldg((const float4*)(X + (size_t)c3 * DIMV) + lane);
            float v0 = __shfl_sync(FM, v, j + 0);
            float v1 = __shfl_sync(FM, v, j + 1);
            float v2 = __shfl_sync(FM, v, j + 2);
            float v3 = __shfl_sync(FM, v, j + 3);
            acc.x += v0 * x0.x; acc.y += v0 * x0.y; acc.z += v0 * x0.z; acc.w += v0 * x0.w;
            acc.x += v1 * x1.x; acc.y += v1 * x1.y; acc.z += v1 * x1.z; acc.w += v1 * x1.w;
            acc.x += v2 * x2.x; acc.y += v2 * x2.y; acc.z += v2 * x2.z; acc.w += v2 * x2.w;
            acc.x += v3 * x3.x; acc.y += v3 * x3.y; acc.z += v3 * x3.z; acc.w += v3 * x3.w;
        }
        for (; j < m; j++) {
            int cj = __shfl_sync(FM, c, j);
            float vj = __shfl_sync(FM, v, j);
            float4 x = __ldg((const float4*)(X + (size_t)cj * DIMV) + lane);
            acc.x += vj * x.x; acc.y += vj * x.y; acc.z += vj * x.z; acc.w += vj * x.w;
        }
    }
    size_t base = (size_t)w * DIMV + lane * 4;
    if (jb.Y) *(float4*)(jb.Y + base) = acc;
    if (jb.acc) {
        float ss = acc.x * acc.x + acc.y * acc.y + acc.z * acc.z + acc.w * acc.w;
#pragma unroll
        for (int o = 16; o; o >>= 1) ss += __shfl_xor_sync(FM, ss, o);
        float sc = rsqrtf(fmaxf(ss, 1e-12f));
        float4 a = *(const float4*)(jb.acc + base);
        a.x += acc.x * sc; a.y += acc.y * sc; a.z += acc.z * sc; a.w += acc.w * sc;
        *(float4*)(jb.acc + base) = a;
    }
}

__global__ void __launch_bounds__(256) spmm_csr3_kernel(Csr3 a) {
    csr_body(a.j[blockIdx.y]);
}

// ------------------- channel attention mix -------------------
__global__ void __launch_bounds__(256) mix_kernel(
        const float* __restrict__ C0, const float* __restrict__ C1, const float* __restrict__ C2,
        const float* __restrict__ A0, const float* __restrict__ A1, const float* __restrict__ A2,
        const float* __restrict__ S, const float* __restrict__ S2,
        float* __restrict__ out, int nrows) {
    int w = (int)((blockIdx.x * (unsigned)blockDim.x + threadIdx.x) >> 5);
    int lane = threadIdx.x & 31;
    if (w >= nrows) return;
    size_t base = (size_t)w * DIMV + lane * 4;
    float4 v = *(const float4*)(g_attvec + lane * 4);
    float4 c0 = *(const float4*)(C0 + base);
    float4 c1 = *(const float4*)(C1 + base);
    float4 c2 = *(const float4*)(C2 + base);
    if (A0) {
        float4 a0 = *(const float4*)(A0 + base);
        float4 a1 = *(const float4*)(A1 + base);
        float4 a2 = *(const float4*)(A2 + base);
        c0.x += a0.x; c0.y += a0.y; c0.z += a0.z; c0.w += a0.w;
        c1.x += a1.x; c1.y += a1.y; c1.z += a1.z; c1.w += a1.w;
        c2.x += a2.x; c2.y += a2.y; c2.z += a2.z; c2.w += a2.w;
    }
    float w0 = c0.x * v.x + c0.y * v.y + c0.z * v.z + c0.w * v.w;
    float w1 = c1.x * v.x + c1.y * v.y + c1.z * v.z + c1.w * v.w;
    float w2 = c2.x * v.x + c2.y * v.y + c2.z * v.z + c2.w * v.w;
#pragma unroll
    for (int o = 16; o; o >>= 1) {
        w0 += __shfl_xor_sync(0xffffffffu, w0, o);
        w1 += __shfl_xor_sync(0xffffffffu, w1, o);
        w2 += __shfl_xor_sync(0xffffffffu, w2, o);
    }
    float m = fmaxf(w0, fmaxf(w1, w2));
    float e0 = expf(w0 - m), e1 = expf(w1 - m), e2 = expf(w2 - m);
    float inv = 1.f / (e0 + e1 + e2);
    e0 *= inv; e1 *= inv; e2 *= inv;
    float4 s = *(const float4*)(S + base);
    if (S2) {
        float4 s2 = *(const float4*)(S2 + base);
        s.x += s2.x; s.y += s2.y; s.z += s2.z; s.w += s2.w;
    }
    float4 o;
    o.x = e0 * c0.x + e1 * c1.x + e2 * c2.x + 0.5f * s.x;
    o.y = e0 * c0.y + e1 * c1.y + e2 * c2.y + 0.5f * s.y;
    o.z = e0 * c0.z + e1 * c1.z + e2 * c2.z + 0.5f * s.z;
    o.w = e0 * c0.w + e1 * c1.w + e2 * c2.w + 0.5f * s.w;
    *(float4*)(out + base) = o;
}

// ------------------- item output -------------------
__global__ void __launch_bounds__(256) item_out_kernel(const float* __restrict__ ie,
                                                       const float* __restrict__ ia,
                                                       float* __restrict__ out) {
    int i = blockIdx.x * blockDim.x + threadIdx.x;
    if (i < (int)(IFl / 4)) {
        float4 a = __ldg((const float4*)ie + i);
        float4 b = *((const float4*)ia + i);
        a.x += b.x; a.y += b.y; a.z += b.z; a.w += b.w;
        *((float4*)out + i) = a;
    }
}

// ------------------- host orchestration -------------------
extern "C" void kernel_launch(void* const* d_in, const int* in_sizes, int n_in,
                              void* d_out, int out_size) {
    const float* u_emb = (const float*)d_in[0];
    const float* i_emb = (const float*)d_in[1];
    const float* gW = (const float*)d_in[2];
    const float* gB = (const float*)d_in[3];
    const float* att = (const float*)d_in[4];
    const float* attm = (const float*)d_in[5];
    const int* Hr[3] = {(const int*)d_in[6], (const int*)d_in[9], (const int*)d_in[12]};
    const int* Hc[3] = {(const int*)d_in[7], (const int*)d_in[10], (const int*)d_in[13]};
    const float* Hv[3] = {(const float*)d_in[8], (const float*)d_in[11], (const float*)d_in[14]};
    const int* Rr = (const int*)d_in[15];
    const int* Rc = (const int*)d_in[16];
    const float* Rv = (const float*)d_in[17];
    int EH = in_sizes[6], ER = in_sizes[15];
    float* out = (float*)d_out;

    static float* B = nullptr;
    static int *cnt = nullptr, *cur = nullptr, *offs = nullptr, *pcol = nullptr;
    static float* pval = nullptr;
    static size_t smem = (size_t)(DIMV * 132 + GROWS * DIMV) * sizeof(float);
    if (!B) {
        cudaGetSymbolAddress((void**)&B, g_buf);
        cudaGetSymbolAddress((void**)&cnt, g_cnt);
        cudaGetSymbolAddress((void**)&cur, g_cur);
        cudaGetSymbolAddress((void**)&offs, g_offs);
        cudaGetSymbolAddress((void**)&pcol, g_pcol);
        cudaGetSymbolAddress((void**)&pval, g_pval);
        cudaFuncSetAttribute(gate_kernel, cudaFuncAttributeMaxDynamicSharedMemorySize, (int)smem);
    }
    float* accc = B + O_ACCC;
    float* sacc = B + O_SACC;
    float* iacc = B + O_IACC;
    float* curA = B + O_CURA;
    float* i1 = B + O_I1;
    float* s1 = B + O_S1;
    float* gate = B + O_GATE;
    float* mixed = B + O_MIX;

#define GP(c) (gate + (size_t)(c) * UF)
#define CA(c) (curA + (size_t)(c) * UF)
#define AC(c) (accc + (size_t)(c) * UF)

    // CSR job layout
    Build5 bj;
    for (int k = 0; k < 3; k++)
        bj.j[k] = {Hr[k], Hc[k], Hv[k], cnt + k * NU, cur + k * NU, offs + k * (NU + 1),
                   pcol + (size_t)k * EHMAX, pval + (size_t)k * EHMAX, EH, NU};
    bj.j[3] = {Rr, Rc, Rv, cnt + 3 * NU, cur + 3 * NU, offs + 3 * (NU + 1),
               pcol + 3 * (size_t)EHMAX, pval + 3 * (size_t)EHMAX, ER, NU};
    bj.j[4] = {Rc, Rr, Rv, cnt + 4 * NU, cur + 4 * NU, offs + 4 * (NU + 1),
               pcol + 3 * (size_t)EHMAX + ERMAX, pval + 3 * (size_t)EHMAX + ERMAX, ER, NI};

    const int* offsR = bj.j[3].offs;  const int* pcolR = bj.j[3].pcol;  const float* pvalR = bj.j[3].pval;
    const int* offsRT = bj.j[4].offs; const int* pcolRT = bj.j[4].pcol; const float* pvalRT = bj.j[4].pval;

    // zero accumulators + counts
    cudaMemsetAsync(B + O_ACCC, 0, (4 * UF + IFl) * sizeof(float));
    cudaMemsetAsync(cnt, 0, CNT_TOT * sizeof(int));

    attvec_kernel<<<1, 128>>>(att, attm);
    gate_kernel<<<dim3(448, 4), 128, smem>>>(u_emb, gW, gB, gate);

    int maxE = EH > ER ? EH : ER;
    count_kernel<<<dim3((maxE + 255) / 256, 5), 256>>>(bj);
    scan_kernel<<<5, 1024>>>(bj);
    scatter_kernel<<<dim3((maxE + 255) / 256, 5), 256>>>(bj);

    int mixb = (NU + 7) / 8;
    int rowbU = (NU + 7) / 8;   // warp per row, 8 warps/block

    // ---------------- layer 1 ----------------
    mix_kernel<<<mixb, 256>>>(GP(0), GP(1), GP(2), nullptr, nullptr, nullptr,
                              GP(3), nullptr, mixed, NU);
    {
        Csr3 a;
        for (int k = 0; k < 3; k++)
            a.j[k] = {bj.j[k].offs, bj.j[k].pcol, bj.j[k].pval, GP(k), CA(k), AC(k), NU};
        spmm_csr3_kernel<<<dim3(rowbU, 3), 256>>>(a);
        Csr3 r;
        r.j[0] = {offsRT, pcolRT, pvalRT, mixed, i1, iacc, NI};  // new_item = R^T @ mixed
        r.j[1] = {offsR, pcolR, pvalR, i_emb, s1, sacc, NU};     // cur_s = R @ i_emb
        r.j[2] = r.j[0];
        spmm_csr3_kernel<<<dim3(rowbU, 2), 256>>>(r);
    }

    // ---------------- layer 2 ----------------
    mix_kernel<<<mixb, 256>>>(CA(0), CA(1), CA(2), nullptr, nullptr, nullptr,
                              s1, nullptr, mixed, NU);
    {
        Csr3 a;
        for (int k = 0; k < 3; k++)
            a.j[k] = {bj.j[k].offs, bj.j[k].pcol, bj.j[k].pval, CA(k), nullptr, AC(k), NU};
        spmm_csr3_kernel<<<dim3(rowbU, 3), 256>>>(a);
        Csr3 r;
        r.j[0] = {offsRT, pcolRT, pvalRT, mixed, nullptr, iacc, NI}; // l2n(R^T @ mixed2)
        r.j[1] = {offsR, pcolR, pvalR, i1, nullptr, sacc, NU};       // l2n(R @ item1)
        r.j[2] = r.j[0];
        spmm_csr3_kernel<<<dim3(rowbU, 2), 256>>>(r);
    }

    // ---------------- final ----------------
    mix_kernel<<<mixb, 256>>>(GP(0), GP(1), GP(2), AC(0), AC(1), AC(2),
                              GP(3), sacc, out, NU);
    item_out_kernel<<<(int)((IFl / 4 + 255) / 256), 256>>>(i_emb, iacc, out + (size_t)NU * DIMV);
}

// round 5
// speedup vs baseline: 1.7329x; 1.1290x over previous
#include <cuda_runtime.h>
#include <cstdint>
#include <cstring>

#define NU 50000
#define NI 25000
#define DIMV 128
#define GROWS 16
#define EHMAX 600000
#define ERMAX 1000000
#define CHUNK 1024
#define NCHU 49               // chunks for NU
#define OSTR 50016            // padded offs stride (16B-aligned int4 base)

#define UF ((size_t)NU * DIMV)
#define IFl ((size_t)NI * DIMV)

// ------------------- unified float scratch -------------------
#define O_ACCC ((size_t)0)
#define O_SACC (3 * UF)
#define O_IACC (4 * UF)
#define O_CURA (4 * UF + IFl)
#define O_I1   (7 * UF + IFl)
#define O_S1   (7 * UF + 2 * IFl)
#define O_GATE (8 * UF + 2 * IFl)
#define O_MIX  (12 * UF + 2 * IFl)
#define TOTALF (13 * UF + 2 * IFl)

__device__ __align__(16) float g_buf[TOTALF];
__device__ float g_attvec[DIMV];

// ------------------- CSR scratch -------------------
// jobs: 0..2 = H0..H2 (NU rows), 3 = R (NU rows), 4 = RT (NI rows)
#define CNT_TOT (4 * NU + NI)
#define OFFS_TOT (4 * OSTR + NI + 16)
#define PE_TOT (3 * EHMAX + 2 * ERMAX)
__device__ __align__(16) int g_cnt[CNT_TOT];
__device__ __align__(16) int g_cur[CNT_TOT];
__device__ __align__(16) int g_offs[OFFS_TOT];
__device__ __align__(16) int2 g_pair[PE_TOT];
__device__ int g_aux[5 * 64];

// ------------------- attention vector: v = M @ a -------------------
__global__ void attvec_kernel(const float* __restrict__ att, const float* __restrict__ mat) {
    int j = threadIdx.x;
    float s = 0.f;
#pragma unroll 8
    for (int d = 0; d < DIMV; d++) s += mat[j * DIMV + d] * att[d];
    g_attvec[j] = s;
}

// ------------------- gating with packed f32x2 FFMA -------------------
__device__ __forceinline__ void ffma2(unsigned long long& c, unsigned long long a, unsigned long long b) {
    asm("fma.rn.f32x2 %0, %1, %2, %3;" : "=l"(c) : "l"(a), "l"(b), "l"(c));
}

__global__ void __launch_bounds__(128) gate_kernel(const float* __restrict__ U,
                                                   const float* __restrict__ W4,
                                                   const float* __restrict__ B4,
                                                   float* __restrict__ gate_out) {
    extern __shared__ float sm[];
    float* Wt = sm;              // [128][132]
    float* Us = sm + DIMV * 132; // [GROWS][128]
    int t = threadIdx.x;
    int c = blockIdx.y;
    const float* W = W4 + c * DIMV * DIMV;
    float b = B4[c * DIMV + t];
    float* out = gate_out + (size_t)c * UF;
    unsigned long long bp = (unsigned long long)__float_as_uint(b); // (b, 0)

    for (int k = 0; k < DIMV; k++) Wt[t * 132 + k] = W[k * DIMV + t];

    for (int r0 = blockIdx.x * GROWS; r0 < NU; r0 += gridDim.x * GROWS) {
        __syncthreads();
#pragma unroll
        for (int r = 0; r < GROWS; r++) Us[r * DIMV + t] = U[(size_t)(r0 + r) * DIMV + t];
        __syncthreads();
        unsigned long long acc2[GROWS];
#pragma unroll
        for (int r = 0; r < GROWS; r++) acc2[r] = bp;
#pragma unroll 4
        for (int k = 0; k < DIMV; k += 4) {
            ulonglong2 w2 = *(const ulonglong2*)&Wt[t * 132 + k];
#pragma unroll
            for (int r = 0; r < GROWS; r++) {
                ulonglong2 u2 = *(const ulonglong2*)&Us[r * DIMV + k];
                ffma2(acc2[r], u2.x, w2.x);
                ffma2(acc2[r], u2.y, w2.y);
            }
        }
#pragma unroll
        for (int r = 0; r < GROWS; r++) {
            float lo = __uint_as_float((unsigned)acc2[r]);
            float hi = __uint_as_float((unsigned)(acc2[r] >> 32));
            float a = lo + hi;
            float uv = Us[r * DIMV + t];
            out[(size_t)(r0 + r) * DIMV + t] = uv / (1.f + expf(-a));
        }
    }
}

// ------------------- CSR build -------------------
struct BuildJob { const int* rows; const int* cols; const float* vals;
                  int* cnt; int* cur; int* offs; int2* pair; int ne; int nrows; };
struct Build5 { BuildJob j[5]; };

__global__ void __launch_bounds__(256) count_kernel(Build5 a) {
    BuildJob jb = a.j[blockIdx.y];
    int e = blockIdx.x * 256 + threadIdx.x;
    if (e < jb.ne) atomicAdd(jb.cnt + __ldg(jb.rows + e), 1);
}

// phase 1: per-chunk local exclusive scan (into offs) + chunk totals -> aux
__global__ void __launch_bounds__(256) scan_chunks_kernel(Build5 a, int* __restrict__ aux) {
    BuildJob jb = a.j[blockIdx.y];
    int n = jb.nrows;
    int base = blockIdx.x * CHUNK;
    if (base >= n) return;
    int tid = threadIdx.x;
    int lane = tid & 31, wid = tid >> 5;
    int i = base + tid * 4;
    int4 v = make_int4(0, 0, 0, 0);
    if (i < n) v = *(const int4*)(jb.cnt + i);
    int s = v.x + v.y + v.z + v.w;
    int ss = s;
#pragma unroll
    for (int o = 1; o < 32; o <<= 1) { int tt = __shfl_up_sync(0xffffffffu, ss, o); if (lane >= o) ss += tt; }
    __shared__ int wsum[8];
    if (lane == 31) wsum[wid] = ss;
    __syncthreads();
    if (tid < 8) {
        int w = wsum[tid];
#pragma unroll
        for (int o = 1; o < 8; o <<= 1) { int tt = __shfl_up_sync(0xffu, w, o); if (tid >= o) w += tt; }
        wsum[tid] = w;
    }
    __syncthreads();
    int excl = ss - s + (wid ? wsum[wid - 1] : 0);
    if (i < n) {
        int4 e;
        e.x = excl; e.y = excl + v.x; e.z = e.y + v.y; e.w = e.z + v.z;
        *(int4*)(jb.offs + i) = e;
    }
    if (tid == 255) aux[blockIdx.y * 64 + blockIdx.x] = wsum[7];
}

// phase 2: scan chunk totals per job (one warp per job); write offs[n]=total
__global__ void __launch_bounds__(160) scan_aux_kernel(Build5 a, int* __restrict__ aux) {
    int wid = threadIdx.x >> 5;
    if (wid >= 5) return;
    BuildJob jb = a.j[wid];
    int nch = (jb.nrows + CHUNK - 1) / CHUNK;
    int lane = threadIdx.x & 31;
    int carry = 0;
    for (int b0 = 0; b0 < nch; b0 += 32) {
        int idx = b0 + lane;
        int v = (idx < nch) ? aux[wid * 64 + idx] : 0;
        int s = v;
#pragma unroll
        for (int o = 1; o < 32; o <<= 1) { int tt = __shfl_up_sync(0xffffffffu, s, o); if (lane >= o) s += tt; }
        if (idx < nch) aux[wid * 64 + idx] = carry + s - v;
        carry += __shfl_sync(0xffffffffu, s, 31);
    }
    if (lane == 0) jb.offs[jb.nrows] = carry;
}

// phase 3: add chunk base, finalize offs and cur
__global__ void __launch_bounds__(256) scan_apply_kernel(Build5 a, const int* __restrict__ aux) {
    BuildJob jb = a.j[blockIdx.y];
    int n = jb.nrows;
    int base = blockIdx.x * CHUNK;
    if (base >= n) return;
    int add = aux[blockIdx.y * 64 + blockIdx.x];
    int i = base + threadIdx.x * 4;
    if (i < n) {
        int4 e = *(const int4*)(jb.offs + i);
        e.x += add; e.y += add; e.z += add; e.w += add;
        *(int4*)(jb.offs + i) = e;
        *(int4*)(jb.cur + i) = e;
    }
}

__global__ void __launch_bounds__(256) scatter_kernel(Build5 a) {
    BuildJob jb = a.j[blockIdx.y];
    int e = blockIdx.x * 256 + threadIdx.x;
    if (e >= jb.ne) return;
    int r = __ldg(jb.rows + e);
    int p = atomicAdd(jb.cur + r, 1);
    jb.pair[p] = make_int2(__ldg(jb.cols + e), __float_as_int(__ldg(jb.vals + e)));
}

// ------------------- CSR SpMM, warp per row, fused l2norm-accumulate -------------------
struct CsrJob { const int* offs; const int2* pair;
                const float* X; float* Y; float* acc; int nrows; };
struct Csr3 { CsrJob j[3]; };

__device__ __forceinline__ void csr_body(const CsrJob& jb) {
    int w = (int)((blockIdx.x * (unsigned)blockDim.x + threadIdx.x) >> 5);
    int lane = threadIdx.x & 31;
    if (w >= jb.nrows) return;
    const unsigned FM = 0xffffffffu;
    int start = __ldg(jb.offs + w);
    int end = __ldg(jb.offs + w + 1);
    float4 acc = make_float4(0.f, 0.f, 0.f, 0.f);
    const float* X = jb.X;
    for (int b = start; b < end; b += 32) {
        int i = b + lane;
        int c = 0; float v = 0.f;
        if (i < end) { int2 pr = __ldg(jb.pair + i); c = pr.x; v = __int_as_float(pr.y); }
        int m = end - b; if (m > 32) m = 32;
        int j = 0;
        for (; j + 4 <= m; j += 4) {
            int c0 = __shfl_sync(FM, c, j + 0);
            int c1 = __shfl_sync(FM, c, j + 1);
            int c2 = __shfl_sync(FM, c, j + 2);
            int c3 = __shfl_sync(FM, c, j + 3);
            float4 x0 = __ldg((const float4*)(X + (size_t)c0 * DIMV) + lane);
            float4 x1 = __ldg((const float4*)(X + (size_t)c1 * DIMV) + lane);
            float4 x2 = __ldg((const float4*)(X + (size_t)c2 * DIMV) + lane);
            float4 x3 = __ldg((const float4*)(X + (size_t)c3 * DIMV) + lane);
            float v0 = __shfl_sync(FM, v, j + 0);
            float v1 = __shfl_sync(FM, v, j + 1);
            float v2 = __shfl_sync(FM, v, j + 2);
            float v3 = __shfl_sync(FM, v, j + 3);
            acc.x += v0 * x0.x; acc.y += v0 * x0.y; acc.z += v0 * x0.z; acc.w += v0 * x0.w;
            acc.x += v1 * x1.x; acc.y += v1 * x1.y; acc.z += v1 * x1.z; acc.w += v1 * x1.w;
            acc.x += v2 * x2.x; acc.y += v2 * x2.y; acc.z += v2 * x2.z; acc.w += v2 * x2.w;
            acc.x += v3 * x3.x; acc.y += v3 * x3.y; acc.z += v3 * x3.z; acc.w += v3 * x3.w;
        }
        for (; j < m; j++) {
            int cj = __shfl_sync(FM, c, j);
            float vj = __shfl_sync(FM, v, j);
            float4 x = __ldg((const float4*)(X + (size_t)cj * DIMV) + lane);
            acc.x += vj * x.x; acc.y += vj * x.y; acc.z += vj * x.z; acc.w += vj * x.w;
        }
    }
    size_t base = (size_t)w * DIMV + lane * 4;
    if (jb.Y) *(float4*)(jb.Y + base) = acc;
    if (jb.acc) {
        float ss = acc.x * acc.x + acc.y * acc.y + acc.z * acc.z + acc.w * acc.w;
#pragma unroll
        for (int o = 16; o; o >>= 1) ss += __shfl_xor_sync(FM, ss, o);
        float sc = rsqrtf(fmaxf(ss, 1e-12f));
        float4 a = *(const float4*)(jb.acc + base);
        a.x += acc.x * sc; a.y += acc.y * sc; a.z += acc.z * sc; a.w += acc.w * sc;
        *(float4*)(jb.acc + base) = a;
    }
}

__global__ void __launch_bounds__(256) spmm_csr3_kernel(Csr3 a) {
    csr_body(a.j[blockIdx.y]);
}

// ------------------- channel attention mix -------------------
__global__ void __launch_bounds__(256) mix_kernel(
        const float* __restrict__ C0, const float* __restrict__ C1, const float* __restrict__ C2,
        const float* __restrict__ A0, const float* __restrict__ A1, const float* __restrict__ A2,
        const float* __restrict__ S, const float* __restrict__ S2,
        float* __restrict__ out, int nrows) {
    int w = (int)((blockIdx.x * (unsigned)blockDim.x + threadIdx.x) >> 5);
    int lane = threadIdx.x & 31;
    if (w >= nrows) return;
    size_t base = (size_t)w * DIMV + lane * 4;
    float4 v = *(const float4*)(g_attvec + lane * 4);
    float4 c0 = *(const float4*)(C0 + base);
    float4 c1 = *(const float4*)(C1 + base);
    float4 c2 = *(const float4*)(C2 + base);
    if (A0) {
        float4 a0 = *(const float4*)(A0 + base);
        float4 a1 = *(const float4*)(A1 + base);
        float4 a2 = *(const float4*)(A2 + base);
        c0.x += a0.x; c0.y += a0.y; c0.z += a0.z; c0.w += a0.w;
        c1.x += a1.x; c1.y += a1.y; c1.z += a1.z; c1.w += a1.w;
        c2.x += a2.x; c2.y += a2.y; c2.z += a2.z; c2.w += a2.w;
    }
    float w0 = c0.x * v.x + c0.y * v.y + c0.z * v.z + c0.w * v.w;
    float w1 = c1.x * v.x + c1.y * v.y + c1.z * v.z + c1.w * v.w;
    float w2 = c2.x * v.x + c2.y * v.y + c2.z * v.z + c2.w * v.w;
#pragma unroll
    for (int o = 16; o; o >>= 1) {
        w0 += __shfl_xor_sync(0xffffffffu, w0, o);
        w1 += __shfl_xor_sync(0xffffffffu, w1, o);
        w2 += __shfl_xor_sync(0xffffffffu, w2, o);
    }
    float m = fmaxf(w0, fmaxf(w1, w2));
    float e0 = expf(w0 - m), e1 = expf(w1 - m), e2 = expf(w2 - m);
    float inv = 1.f / (e0 + e1 + e2);
    e0 *= inv; e1 *= inv; e2 *= inv;
    float4 s = *(const float4*)(S + base);
    if (S2) {
        float4 s2 = *(const float4*)(S2 + base);
        s.x += s2.x; s.y += s2.y; s.z += s2.z; s.w += s2.w;
    }
    float4 o;
    o.x = e0 * c0.x + e1 * c1.x + e2 * c2.x + 0.5f * s.x;
    o.y = e0 * c0.y + e1 * c1.y + e2 * c2.y + 0.5f * s.y;
    o.z = e0 * c0.z + e1 * c1.z + e2 * c2.z + 0.5f * s.z;
    o.w = e0 * c0.w + e1 * c1.w + e2 * c2.w + 0.5f * s.w;
    *(float4*)(out + base) = o;
}

// ------------------- item output -------------------
__global__ void __launch_bounds__(256) item_out_kernel(const float* __restrict__ ie,
                                                       const float* __restrict__ ia,
                                                       float* __restrict__ out) {
    int i = blockIdx.x * blockDim.x + threadIdx.x;
    if (i < (int)(IFl / 4)) {
        float4 a = __ldg((const float4*)ie + i);
        float4 b = *((const float4*)ia + i);
        a.x += b.x; a.y += b.y; a.z += b.z; a.w += b.w;
        *((float4*)out + i) = a;
    }
}

// ------------------- host orchestration -------------------
extern "C" void kernel_launch(void* const* d_in, const int* in_sizes, int n_in,
                              void* d_out, int out_size) {
    const float* u_emb = (const float*)d_in[0];
    const float* i_emb = (const float*)d_in[1];
    const float* gW = (const float*)d_in[2];
    const float* gB = (const float*)d_in[3];
    const float* att = (const float*)d_in[4];
    const float* attm = (const float*)d_in[5];
    const int* Hr[3] = {(const int*)d_in[6], (const int*)d_in[9], (const int*)d_in[12]};
    const int* Hc[3] = {(const int*)d_in[7], (const int*)d_in[10], (const int*)d_in[13]};
    const float* Hv[3] = {(const float*)d_in[8], (const float*)d_in[11], (const float*)d_in[14]};
    const int* Rr = (const int*)d_in[15];
    const int* Rc = (const int*)d_in[16];
    const float* Rv = (const float*)d_in[17];
    int EH = in_sizes[6], ER = in_sizes[15];
    float* out = (float*)d_out;

    static float* B = nullptr;
    static int *cnt = nullptr, *cur = nullptr, *offs = nullptr, *aux = nullptr;
    static int2* pair = nullptr;
    static size_t smem = (size_t)(DIMV * 132 + GROWS * DIMV) * sizeof(float);
    if (!B) {
        cudaGetSymbolAddress((void**)&B, g_buf);
        cudaGetSymbolAddress((void**)&cnt, g_cnt);
        cudaGetSymbolAddress((void**)&cur, g_cur);
        cudaGetSymbolAddress((void**)&offs, g_offs);
        cudaGetSymbolAddress((void**)&pair, g_pair);
        cudaGetSymbolAddress((void**)&aux, g_aux);
        cudaFuncSetAttribute(gate_kernel, cudaFuncAttributeMaxDynamicSharedMemorySize, (int)smem);
    }
    float* accc = B + O_ACCC;
    float* sacc = B + O_SACC;
    float* iacc = B + O_IACC;
    float* curA = B + O_CURA;
    float* i1 = B + O_I1;
    float* s1 = B + O_S1;
    float* gate = B + O_GATE;
    float* mixed = B + O_MIX;

#define GP(c) (gate + (size_t)(c) * UF)
#define CA(c) (curA + (size_t)(c) * UF)
#define AC(c) (accc + (size_t)(c) * UF)

    Build5 bj;
    for (int k = 0; k < 3; k++)
        bj.j[k] = {Hr[k], Hc[k], Hv[k], cnt + k * NU, cur + k * NU, offs + k * OSTR,
                   pair + (size_t)k * EHMAX, EH, NU};
    bj.j[3] = {Rr, Rc, Rv, cnt + 3 * NU, cur + 3 * NU, offs + 3 * OSTR,
               pair + 3 * (size_t)EHMAX, ER, NU};
    bj.j[4] = {Rc, Rr, Rv, cnt + 4 * NU, cur + 4 * NU, offs + 4 * OSTR,
               pair + 3 * (size_t)EHMAX + ERMAX, ER, NI};

    const int* offsR = bj.j[3].offs;  const int2* pairR = bj.j[3].pair;
    const int* offsRT = bj.j[4].offs; const int2* pairRT = bj.j[4].pair;

    cudaMemsetAsync(B + O_ACCC, 0, (4 * UF + IFl) * sizeof(float));
    cudaMemsetAsync(cnt, 0, CNT_TOT * sizeof(int));

    attvec_kernel<<<1, 128>>>(att, attm);
    gate_kernel<<<dim3(448, 4), 128, smem>>>(u_emb, gW, gB, gate);

    int maxE = EH > ER ? EH : ER;
    count_kernel<<<dim3((maxE + 255) / 256, 5), 256>>>(bj);
    scan_chunks_kernel<<<dim3(NCHU, 5), 256>>>(bj, aux);
    scan_aux_kernel<<<1, 160>>>(bj, aux);
    scan_apply_kernel<<<dim3(NCHU, 5), 256>>>(bj, aux);
    scatter_kernel<<<dim3((maxE + 255) / 256, 5), 256>>>(bj);

    int mixb = (NU + 7) / 8;
    int rowbU = (NU + 7) / 8;

    // ---------------- layer 1 ----------------
    mix_kernel<<<mixb, 256>>>(GP(0), GP(1), GP(2), nullptr, nullptr, nullptr,
                              GP(3), nullptr, mixed, NU);
    {
        Csr3 a;
        for (int k = 0; k < 3; k++)
            a.j[k] = {bj.j[k].offs, bj.j[k].pair, GP(k), CA(k), AC(k), NU};
        spmm_csr3_kernel<<<dim3(rowbU, 3), 256>>>(a);
        Csr3 r;
        r.j[0] = {offsRT, pairRT, mixed, i1, iacc, NI};
        r.j[1] = {offsR, pairR, i_emb, s1, sacc, NU};
        r.j[2] = r.j[0];
        spmm_csr3_kernel<<<dim3(rowbU, 2), 256>>>(r);
    }

    // ---------------- layer 2 ----------------
    mix_kernel<<<mixb, 256>>>(CA(0), CA(1), CA(2), nullptr, nullptr, nullptr,
                              s1, nullptr, mixed, NU);
    {
        Csr3 a;
        for (int k = 0; k < 3; k++)
            a.j[k] = {bj.j[k].offs, bj.j[k].pair, CA(k), nullptr, AC(k), NU};
        spmm_csr3_kernel<<<dim3(rowbU, 3), 256>>>(a);
        Csr3 r;
        r.j[0] = {offsRT, pairRT, mixed, nullptr, iacc, NI};
        r.j[1] = {offsR, pairR, i1, nullptr, sacc, NU};
        r.j[2] = r.j[0];
        spmm_csr3_kernel<<<dim3(rowbU, 2), 256>>>(r);
    }

    // ---------------- final ----------------
    mix_kernel<<<mixb, 256>>>(GP(0), GP(1), GP(2), AC(0), AC(1), AC(2),
                              GP(3), sacc, out, NU);
    item_out_kernel<<<(int)((IFl / 4 + 255) / 256), 256>>>(i_emb, iacc, out + (size_t)NU * DIMV);
}

// round 6
// speedup vs baseline: 1.8875x; 1.0892x over previous
#include <cuda_runtime.h>
#include <cuda_fp16.h>
#include <cstdint>

#define NU 50000
#define NI 25000
#define DIMV 128
#define GROWS 16
#define EHMAX 600000
#define ERMAX 1000000
#define CHUNK 1024
#define NCHU 49
#define OSTR 50016

#define UF ((size_t)NU * DIMV)
#define IFl ((size_t)NI * DIMV)

// ------------------- fp32 scratch -------------------
// accc[3UF] | sacc[UF] | iacc[IF]  <- zero group
// curA[3UF] | s1[UF] | gate[4UF]
#define O_ACCC ((size_t)0)
#define O_SACC (3 * UF)
#define O_IACC (4 * UF)
#define O_CURA (4 * UF + IFl)
#define O_S1   (7 * UF + IFl)
#define O_GATE (8 * UF + IFl)
#define TOTALF (12 * UF + IFl)
__device__ __align__(16) float g_buf[TOTALF];

// ------------------- fp16 scratch -------------------
// gate16[3UF] | curA16[3UF] | mix16[UF] | i1_16[IF] | iemb16[IF]
#define H_GATE ((size_t)0)
#define H_CURA (3 * UF)
#define H_MIX  (6 * UF)
#define H_I1   (7 * UF)
#define H_IEMB (7 * UF + IFl)
#define TOTALH (7 * UF + 2 * IFl)
__device__ __align__(16) __half g_hbuf[TOTALH];

__device__ float g_attvec[DIMV];

// ------------------- CSR scratch -------------------
#define CNT_TOT (4 * NU + NI)
#define OFFS_TOT (4 * OSTR + NI + 16)
#define PE_TOT (3 * EHMAX + 2 * ERMAX)
__device__ __align__(16) int g_cnt[CNT_TOT];
__device__ __align__(16) int g_cur[CNT_TOT];
__device__ __align__(16) int g_offs[OFFS_TOT];
__device__ __align__(16) int2 g_pair[PE_TOT];
__device__ int g_aux[5 * 64];

// ------------------- attention vector: v = M @ a -------------------
__global__ void attvec_kernel(const float* __restrict__ att, const float* __restrict__ mat) {
    int j = threadIdx.x;
    float s = 0.f;
#pragma unroll 8
    for (int d = 0; d < DIMV; d++) s += mat[j * DIMV + d] * att[d];
    g_attvec[j] = s;
}

// ------------------- f32 -> f16 conversion -------------------
__global__ void __launch_bounds__(256) f2h_kernel(const float* __restrict__ src,
                                                  __half* __restrict__ dst, int n4) {
    int i = blockIdx.x * 256 + threadIdx.x;
    if (i < n4) {
        float4 v = __ldg((const float4*)src + i);
        union { __half2 h[2]; uint2 u; } cv;
        cv.h[0] = __floats2half2_rn(v.x, v.y);
        cv.h[1] = __floats2half2_rn(v.z, v.w);
        *(uint2*)(dst + (size_t)i * 4) = cv.u;
    }
}

// ------------------- gating with packed f32x2 FFMA -------------------
__device__ __forceinline__ void ffma2(unsigned long long& c, unsigned long long a, unsigned long long b) {
    asm("fma.rn.f32x2 %0, %1, %2, %3;" : "=l"(c) : "l"(a), "l"(b), "l"(c));
}

__global__ void __launch_bounds__(128) gate_kernel(const float* __restrict__ U,
                                                   const float* __restrict__ W4,
                                                   const float* __restrict__ B4,
                                                   float* __restrict__ gate_out,
                                                   __half* __restrict__ gate16) {
    extern __shared__ float sm[];
    float* Wt = sm;
    float* Us = sm + DIMV * 132;
    int t = threadIdx.x;
    int c = blockIdx.y;
    const float* W = W4 + c * DIMV * DIMV;
    float b = B4[c * DIMV + t];
    float* out = gate_out + (size_t)c * UF;
    __half* out16 = (c < 3) ? (gate16 + (size_t)c * UF) : nullptr;
    unsigned long long bp = (unsigned long long)__float_as_uint(b);

    for (int k = 0; k < DIMV; k++) Wt[t * 132 + k] = W[k * DIMV + t];

    for (int r0 = blockIdx.x * GROWS; r0 < NU; r0 += gridDim.x * GROWS) {
        __syncthreads();
#pragma unroll
        for (int r = 0; r < GROWS; r++) Us[r * DIMV + t] = U[(size_t)(r0 + r) * DIMV + t];
        __syncthreads();
        unsigned long long acc2[GROWS];
#pragma unroll
        for (int r = 0; r < GROWS; r++) acc2[r] = bp;
#pragma unroll 4
        for (int k = 0; k < DIMV; k += 4) {
            ulonglong2 w2 = *(const ulonglong2*)&Wt[t * 132 + k];
#pragma unroll
            for (int r = 0; r < GROWS; r++) {
                ulonglong2 u2 = *(const ulonglong2*)&Us[r * DIMV + k];
                ffma2(acc2[r], u2.x, w2.x);
                ffma2(acc2[r], u2.y, w2.y);
            }
        }
#pragma unroll
        for (int r = 0; r < GROWS; r++) {
            float lo = __uint_as_float((unsigned)acc2[r]);
            float hi = __uint_as_float((unsigned)(acc2[r] >> 32));
            float a = lo + hi;
            float uv = Us[r * DIMV + t];
            float g = uv / (1.f + expf(-a));
            out[(size_t)(r0 + r) * DIMV + t] = g;
            if (out16) out16[(size_t)(r0 + r) * DIMV + t] = __float2half_rn(g);
        }
    }
}

// ------------------- CSR build -------------------
struct BuildJob { const int* rows; const int* cols; const float* vals;
                  int* cnt; int* cur; int* offs; int2* pair; int ne; int nrows; };
struct Build5 { BuildJob j[5]; };

__global__ void __launch_bounds__(256) count_kernel(Build5 a) {
    BuildJob jb = a.j[blockIdx.y];
    int e = blockIdx.x * 256 + threadIdx.x;
    if (e < jb.ne) atomicAdd(jb.cnt + __ldg(jb.rows + e), 1);
}

__global__ void __launch_bounds__(256) scan_chunks_kernel(Build5 a, int* __restrict__ aux) {
    BuildJob jb = a.j[blockIdx.y];
    int n = jb.nrows;
    int base = blockIdx.x * CHUNK;
    if (base >= n) return;
    int tid = threadIdx.x;
    int lane = tid & 31, wid = tid >> 5;
    int i = base + tid * 4;
    int4 v = make_int4(0, 0, 0, 0);
    if (i < n) v = *(const int4*)(jb.cnt + i);
    int s = v.x + v.y + v.z + v.w;
    int ss = s;
#pragma unroll
    for (int o = 1; o < 32; o <<= 1) { int tt = __shfl_up_sync(0xffffffffu, ss, o); if (lane >= o) ss += tt; }
    __shared__ int wsum[8];
    if (lane == 31) wsum[wid] = ss;
    __syncthreads();
    if (tid < 8) {
        int w = wsum[tid];
#pragma unroll
        for (int o = 1; o < 8; o <<= 1) { int tt = __shfl_up_sync(0xffu, w, o); if (tid >= o) w += tt; }
        wsum[tid] = w;
    }
    __syncthreads();
    int excl = ss - s + (wid ? wsum[wid - 1] : 0);
    if (i < n) {
        int4 e;
        e.x = excl; e.y = excl + v.x; e.z = e.y + v.y; e.w = e.z + v.z;
        *(int4*)(jb.offs + i) = e;
    }
    if (tid == 255) aux[blockIdx.y * 64 + blockIdx.x] = wsum[7];
}

__global__ void __launch_bounds__(160) scan_aux_kernel(Build5 a, int* __restrict__ aux) {
    int wid = threadIdx.x >> 5;
    if (wid >= 5) return;
    BuildJob jb = a.j[wid];
    int nch = (jb.nrows + CHUNK - 1) / CHUNK;
    int lane = threadIdx.x & 31;
    int carry = 0;
    for (int b0 = 0; b0 < nch; b0 += 32) {
        int idx = b0 + lane;
        int v = (idx < nch) ? aux[wid * 64 + idx] : 0;
        int s = v;
#pragma unroll
        for (int o = 1; o < 32; o <<= 1) { int tt = __shfl_up_sync(0xffffffffu, s, o); if (lane >= o) s += tt; }
        if (idx < nch) aux[wid * 64 + idx] = carry + s - v;
        carry += __shfl_sync(0xffffffffu, s, 31);
    }
    if (lane == 0) jb.offs[jb.nrows] = carry;
}

__global__ void __launch_bounds__(256) scan_apply_kernel(Build5 a, const int* __restrict__ aux) {
    BuildJob jb = a.j[blockIdx.y];
    int n = jb.nrows;
    int base = blockIdx.x * CHUNK;
    if (base >= n) return;
    int add = aux[blockIdx.y * 64 + blockIdx.x];
    int i = base + threadIdx.x * 4;
    if (i < n) {
        int4 e = *(const int4*)(jb.offs + i);
        e.x += add; e.y += add; e.z += add; e.w += add;
        *(int4*)(jb.offs + i) = e;
        *(int4*)(jb.cur + i) = e;
    }
}

__global__ void __launch_bounds__(256) scatter_kernel(Build5 a) {
    BuildJob jb = a.j[blockIdx.y];
    int e = blockIdx.x * 256 + threadIdx.x;
    if (e >= jb.ne) return;
    int r = __ldg(jb.rows + e);
    int p = atomicAdd(jb.cur + r, 1);
    jb.pair[p] = make_int2(__ldg(jb.cols + e), __float_as_int(__ldg(jb.vals + e)));
}

// ------------------- CSR SpMM (fp16 gathers), warp per row, fused epilogues -------------------
struct CsrJob { const int* offs; const int2* pair; const __half* X;
                float* Y; __half* Y16; float* acc; int nrows; };
struct Csr3 { CsrJob j[3]; };

__device__ __forceinline__ void fma_h(float4& acc, float v, uint2 raw) {
    __half2 h0 = *(__half2*)&raw.x;
    __half2 h1 = *(__half2*)&raw.y;
    float2 f0 = __half22float2(h0);
    float2 f1 = __half22float2(h1);
    acc.x += v * f0.x; acc.y += v * f0.y; acc.z += v * f1.x; acc.w += v * f1.y;
}

__device__ __forceinline__ void csr_body(const CsrJob& jb) {
    int w = (int)((blockIdx.x * (unsigned)blockDim.x + threadIdx.x) >> 5);
    int lane = threadIdx.x & 31;
    if (w >= jb.nrows) return;
    const unsigned FM = 0xffffffffu;
    int start = __ldg(jb.offs + w);
    int end = __ldg(jb.offs + w + 1);
    float4 acc = make_float4(0.f, 0.f, 0.f, 0.f);
    const __half* X = jb.X;
    for (int b = start; b < end; b += 32) {
        int i = b + lane;
        int c = 0; float v = 0.f;
        if (i < end) { int2 pr = __ldg(jb.pair + i); c = pr.x; v = __int_as_float(pr.y); }
        int m = end - b; if (m > 32) m = 32;
        int j = 0;
        for (; j + 4 <= m; j += 4) {
            int c0 = __shfl_sync(FM, c, j + 0);
            int c1 = __shfl_sync(FM, c, j + 1);
            int c2 = __shfl_sync(FM, c, j + 2);
            int c3 = __shfl_sync(FM, c, j + 3);
            uint2 x0 = __ldg((const uint2*)(X + (size_t)c0 * DIMV) + lane);
            uint2 x1 = __ldg((const uint2*)(X + (size_t)c1 * DIMV) + lane);
            uint2 x2 = __ldg((const uint2*)(X + (size_t)c2 * DIMV) + lane);
            uint2 x3 = __ldg((const uint2*)(X + (size_t)c3 * DIMV) + lane);
            float v0 = __shfl_sync(FM, v, j + 0);
            float v1 = __shfl_sync(FM, v, j + 1);
            float v2 = __shfl_sync(FM, v, j + 2);
            float v3 = __shfl_sync(FM, v, j + 3);
            fma_h(acc, v0, x0);
            fma_h(acc, v1, x1);
            fma_h(acc, v2, x2);
            fma_h(acc, v3, x3);
        }
        for (; j < m; j++) {
            int cj = __shfl_sync(FM, c, j);
            float vj = __shfl_sync(FM, v, j);
            uint2 x = __ldg((const uint2*)(X + (size_t)cj * DIMV) + lane);
            fma_h(acc, vj, x);
        }
    }
    size_t base = (size_t)w * DIMV + lane * 4;
    if (jb.Y) *(float4*)(jb.Y + base) = acc;
    if (jb.Y16) {
        union { __half2 h[2]; uint2 u; } cv;
        cv.h[0] = __floats2half2_rn(acc.x, acc.y);
        cv.h[1] = __floats2half2_rn(acc.z, acc.w);
        *(uint2*)(jb.Y16 + base) = cv.u;
    }
    if (jb.acc) {
        float ss = acc.x * acc.x + acc.y * acc.y + acc.z * acc.z + acc.w * acc.w;
#pragma unroll
        for (int o = 16; o; o >>= 1) ss += __shfl_xor_sync(FM, ss, o);
        float sc = rsqrtf(fmaxf(ss, 1e-12f));
        float4 a = *(const float4*)(jb.acc + base);
        a.x += acc.x * sc; a.y += acc.y * sc; a.z += acc.z * sc; a.w += acc.w * sc;
        *(float4*)(jb.acc + base) = a;
    }
}

__global__ void __launch_bounds__(256) spmm_csr3_kernel(Csr3 a) {
    csr_body(a.j[blockIdx.y]);
}

// ------------------- channel attention mix -------------------
__global__ void __launch_bounds__(256) mix_kernel(
        const float* __restrict__ C0, const float* __restrict__ C1, const float* __restrict__ C2,
        const float* __restrict__ A0, const float* __restrict__ A1, const float* __restrict__ A2,
        const float* __restrict__ S, const float* __restrict__ S2,
        float* __restrict__ out32, __half* __restrict__ out16, int nrows) {
    int w = (int)((blockIdx.x * (unsigned)blockDim.x + threadIdx.x) >> 5);
    int lane = threadIdx.x & 31;
    if (w >= nrows) return;
    size_t base = (size_t)w * DIMV + lane * 4;
    float4 v = *(const float4*)(g_attvec + lane * 4);
    float4 c0 = *(const float4*)(C0 + base);
    float4 c1 = *(const float4*)(C1 + base);
    float4 c2 = *(const float4*)(C2 + base);
    if (A0) {
        float4 a0 = *(const float4*)(A0 + base);
        float4 a1 = *(const float4*)(A1 + base);
        float4 a2 = *(const float4*)(A2 + base);
        c0.x += a0.x; c0.y += a0.y; c0.z += a0.z; c0.w += a0.w;
        c1.x += a1.x; c1.y += a1.y; c1.z += a1.z; c1.w += a1.w;
        c2.x += a2.x; c2.y += a2.y; c2.z += a2.z; c2.w += a2.w;
    }
    float w0 = c0.x * v.x + c0.y * v.y + c0.z * v.z + c0.w * v.w;
    float w1 = c1.x * v.x + c1.y * v.y + c1.z * v.z + c1.w * v.w;
    float w2 = c2.x * v.x + c2.y * v.y + c2.z * v.z + c2.w * v.w;
#pragma unroll
    for (int o = 16; o; o >>= 1) {
        w0 += __shfl_xor_sync(0xffffffffu, w0, o);
        w1 += __shfl_xor_sync(0xffffffffu, w1, o);
        w2 += __shfl_xor_sync(0xffffffffu, w2, o);
    }
    float m = fmaxf(w0, fmaxf(w1, w2));
    float e0 = expf(w0 - m), e1 = expf(w1 - m), e2 = expf(w2 - m);
    float inv = 1.f / (e0 + e1 + e2);
    e0 *= inv; e1 *= inv; e2 *= inv;
    float4 s = *(const float4*)(S + base);
    if (S2) {
        float4 s2 = *(const float4*)(S2 + base);
        s.x += s2.x; s.y += s2.y; s.z += s2.z; s.w += s2.w;
    }
    float4 o;
    o.x = e0 * c0.x + e1 * c1.x + e2 * c2.x + 0.5f * s.x;
    o.y = e0 * c0.y + e1 * c1.y + e2 * c2.y + 0.5f * s.y;
    o.z = e0 * c0.z + e1 * c1.z + e2 * c2.z + 0.5f * s.z;
    o.w = e0 * c0.w + e1 * c1.w + e2 * c2.w + 0.5f * s.w;
    if (out32) *(float4*)(out32 + base) = o;
    if (out16) {
        union { __half2 h[2]; uint2 u; } cv;
        cv.h[0] = __floats2half2_rn(o.x, o.y);
        cv.h[1] = __floats2half2_rn(o.z, o.w);
        *(uint2*)(out16 + base) = cv.u;
    }
}

// ------------------- item output -------------------
__global__ void __launch_bounds__(256) item_out_kernel(const float* __restrict__ ie,
                                                       const float* __restrict__ ia,
                                                       float* __restrict__ out) {
    int i = blockIdx.x * blockDim.x + threadIdx.x;
    if (i < (int)(IFl / 4)) {
        float4 a = __ldg((const float4*)ie + i);
        float4 b = *((const float4*)ia + i);
        a.x += b.x; a.y += b.y; a.z += b.z; a.w += b.w;
        *((float4*)out + i) = a;
    }
}

// ------------------- host orchestration -------------------
extern "C" void kernel_launch(void* const* d_in, const int* in_sizes, int n_in,
                              void* d_out, int out_size) {
    const float* u_emb = (const float*)d_in[0];
    const float* i_emb = (const float*)d_in[1];
    const float* gW = (const float*)d_in[2];
    const float* gB = (const float*)d_in[3];
    const float* att = (const float*)d_in[4];
    const float* attm = (const float*)d_in[5];
    const int* Hr[3] = {(const int*)d_in[6], (const int*)d_in[9], (const int*)d_in[12]};
    const int* Hc[3] = {(const int*)d_in[7], (const int*)d_in[10], (const int*)d_in[13]};
    const float* Hv[3] = {(const float*)d_in[8], (const float*)d_in[11], (const float*)d_in[14]};
    const int* Rr = (const int*)d_in[15];
    const int* Rc = (const int*)d_in[16];
    const float* Rv = (const float*)d_in[17];
    int EH = in_sizes[6], ER = in_sizes[15];
    float* out = (float*)d_out;

    static float* B = nullptr;
    static __half* H = nullptr;
    static int *cnt = nullptr, *cur = nullptr, *offs = nullptr, *aux = nullptr;
    static int2* pair = nullptr;
    static size_t smem = (size_t)(DIMV * 132 + GROWS * DIMV) * sizeof(float);
    if (!B) {
        cudaGetSymbolAddress((void**)&B, g_buf);
        cudaGetSymbolAddress((void**)&H, g_hbuf);
        cudaGetSymbolAddress((void**)&cnt, g_cnt);
        cudaGetSymbolAddress((void**)&cur, g_cur);
        cudaGetSymbolAddress((void**)&offs, g_offs);
        cudaGetSymbolAddress((void**)&pair, g_pair);
        cudaGetSymbolAddress((void**)&aux, g_aux);
        cudaFuncSetAttribute(gate_kernel, cudaFuncAttributeMaxDynamicSharedMemorySize, (int)smem);
    }
    float* accc = B + O_ACCC;
    float* sacc = B + O_SACC;
    float* iacc = B + O_IACC;
    float* curA = B + O_CURA;
    float* s1 = B + O_S1;
    float* gate = B + O_GATE;
    __half* gate16 = H + H_GATE;
    __half* curA16 = H + H_CURA;
    __half* mix16 = H + H_MIX;
    __half* i1_16 = H + H_I1;
    __half* iemb16 = H + H_IEMB;

#define GP(c) (gate + (size_t)(c) * UF)
#define GP16(c) (gate16 + (size_t)(c) * UF)
#define CA(c) (curA + (size_t)(c) * UF)
#define CA16(c) (curA16 + (size_t)(c) * UF)
#define AC(c) (accc + (size_t)(c) * UF)

    Build5 bj;
    for (int k = 0; k < 3; k++)
        bj.j[k] = {Hr[k], Hc[k], Hv[k], cnt + k * NU, cur + k * NU, offs + k * OSTR,
                   pair + (size_t)k * EHMAX, EH, NU};
    bj.j[3] = {Rr, Rc, Rv, cnt + 3 * NU, cur + 3 * NU, offs + 3 * OSTR,
               pair + 3 * (size_t)EHMAX, ER, NU};
    bj.j[4] = {Rc, Rr, Rv, cnt + 4 * NU, cur + 4 * NU, offs + 4 * OSTR,
               pair + 3 * (size_t)EHMAX + ERMAX, ER, NI};

    const int* offsR = bj.j[3].offs;  const int2* pairR = bj.j[3].pair;
    const int* offsRT = bj.j[4].offs; const int2* pairRT = bj.j[4].pair;

    cudaMemsetAsync(B + O_ACCC, 0, (4 * UF + IFl) * sizeof(float));
    cudaMemsetAsync(cnt, 0, CNT_TOT * sizeof(int));

    attvec_kernel<<<1, 128>>>(att, attm);
    f2h_kernel<<<(int)((IFl / 4 + 255) / 256), 256>>>(i_emb, iemb16, (int)(IFl / 4));
    gate_kernel<<<dim3(448, 4), 128, smem>>>(u_emb, gW, gB, gate, gate16);

    int maxE = EH > ER ? EH : ER;
    count_kernel<<<dim3((maxE + 255) / 256, 5), 256>>>(bj);
    scan_chunks_kernel<<<dim3(NCHU, 5), 256>>>(bj, aux);
    scan_aux_kernel<<<1, 160>>>(bj, aux);
    scan_apply_kernel<<<dim3(NCHU, 5), 256>>>(bj, aux);
    scatter_kernel<<<dim3((maxE + 255) / 256, 5), 256>>>(bj);

    int mixb = (NU + 7) / 8;
    int rowbU = (NU + 7) / 8;

    // ---------------- layer 1 ----------------
    mix_kernel<<<mixb, 256>>>(GP(0), GP(1), GP(2), nullptr, nullptr, nullptr,
                              GP(3), nullptr, nullptr, mix16, NU);
    {
        Csr3 a;
        for (int k = 0; k < 3; k++)
            a.j[k] = {bj.j[k].offs, bj.j[k].pair, GP16(k), CA(k), CA16(k), AC(k), NU};
        spmm_csr3_kernel<<<dim3(rowbU, 3), 256>>>(a);
        Csr3 r;
        r.j[0] = {offsRT, pairRT, mix16, nullptr, i1_16, iacc, NI};  // item1 = R^T @ mixed
        r.j[1] = {offsR, pairR, iemb16, s1, nullptr, sacc, NU};      // s1 = R @ i_emb
        r.j[2] = r.j[0];
        spmm_csr3_kernel<<<dim3(rowbU, 2), 256>>>(r);
    }

    // ---------------- layer 2 ----------------
    mix_kernel<<<mixb, 256>>>(CA(0), CA(1), CA(2), nullptr, nullptr, nullptr,
                              s1, nullptr, nullptr, mix16, NU);
    {
        Csr3 a;
        for (int k = 0; k < 3; k++)
            a.j[k] = {bj.j[k].offs, bj.j[k].pair, CA16(k), nullptr, nullptr, AC(k), NU};
        spmm_csr3_kernel<<<dim3(rowbU, 3), 256>>>(a);
        Csr3 r;
        r.j[0] = {offsRT, pairRT, mix16, nullptr, nullptr, iacc, NI};  // l2n(R^T @ mixed2)
        r.j[1] = {offsR, pairR, i1_16, nullptr, nullptr, sacc, NU};    // l2n(R @ item1)
        r.j[2] = r.j[0];
        spmm_csr3_kernel<<<dim3(rowbU, 2), 256>>>(r);
    }

    // ---------------- final ----------------
    mix_kernel<<<mixb, 256>>>(GP(0), GP(1), GP(2), AC(0), AC(1), AC(2),
                              GP(3), sacc, out, nullptr, NU);
    item_out_kernel<<<(int)((IFl / 4 + 255) / 256), 256>>>(i_emb, iacc, out + (size_t)NU * DIMV);
}